// round 11
// baseline (speedup 1.0000x reference)
#include <cuda_runtime.h>
#include <cuda_fp16.h>
#include <stdint.h>

#define S_LEN 512
#define KV    128
#define NBLK  1036      // 148 SMs x 7 resident blocks (persistent)

// fused weight arena offsets (halves)
#define OW0  0        // Ws0: paired-kt, 8 blocks * 256
#define OW1  2048     // Ws1: nt-paired, 4 blocks * 256
#define OC0S 3072     // Wc0[:, :16] n-paired, 4 blocks * 256 (bias/SH part)
#define OC0D 4096     // Wc0[:,16:31] n-paired, 4 blocks * 256 (dc part, padded)
#define OC1  5120     // Wc1: paired-kt, 16 blocks * 256
#define OC2  9216     // Wc2: single-nt unpaired, 4 blocks * 128
#define WTOT 9728

__device__ __forceinline__ void mma16816(float* d, const uint32_t* a,
                                         uint32_t b0, uint32_t b1) {
    asm volatile("mma.sync.aligned.m16n8k16.row.col.f32.f16.f16.f32 "
        "{%0,%1,%2,%3},{%4,%5,%6,%7},{%8,%9},{%0,%1,%2,%3};"
        : "+f"(d[0]), "+f"(d[1]), "+f"(d[2]), "+f"(d[3])
        : "r"(a[0]), "r"(a[1]), "r"(a[2]), "r"(a[3]), "r"(b0), "r"(b1));
}
// D = A*B + 0
__device__ __forceinline__ void mma16816_zc(float* d, const uint32_t* a,
                                            uint32_t b0, uint32_t b1) {
    asm volatile("mma.sync.aligned.m16n8k16.row.col.f32.f16.f16.f32 "
        "{%0,%1,%2,%3},{%4,%5,%6,%7},{%8,%9},{%10,%11,%12,%13};"
        : "=f"(d[0]), "=f"(d[1]), "=f"(d[2]), "=f"(d[3])
        : "r"(a[0]), "r"(a[1]), "r"(a[2]), "r"(a[3]), "r"(b0), "r"(b1),
          "f"(0.f), "f"(0.f), "f"(0.f), "f"(0.f));
}
// D = A*B + {c0,c1,c0,c1}
__device__ __forceinline__ void mma16816_c(float* d, const uint32_t* a,
                                           uint32_t b0, uint32_t b1,
                                           float c0, float c1) {
    asm volatile("mma.sync.aligned.m16n8k16.row.col.f32.f16.f16.f32 "
        "{%0,%1,%2,%3},{%4,%5,%6,%7},{%8,%9},{%10,%11,%10,%11};"
        : "=f"(d[0]), "=f"(d[1]), "=f"(d[2]), "=f"(d[3])
        : "r"(a[0]), "r"(a[1]), "r"(a[2]), "r"(a[3]), "r"(b0), "r"(b1),
          "f"(c0), "f"(c1));
}
__device__ __forceinline__ uint32_t h2nr(float a, float b) {
    __half2 h = __floats2half2_rn(a, b);
    return *(uint32_t*)&h;
}
__device__ __forceinline__ uint32_t h2relu(float a, float b) {
    __half2 h = __floats2half2_rn(a, b);
    h = __hmax2(h, __half2_raw{0, 0});
    return *(uint32_t*)&h;
}

// paired-kt lane-packed repack (PERM = layer-1 K permutation)
template<int NT, int KT, bool PERM>
__device__ __forceinline__ void stage_w(const float* __restrict__ W, int nrows, int kin,
                                        __half* dst, int t)
{
    constexpr int KTP = KT / 2;
    for (int idx = t; idx < NT * KTP * 32; idx += 128) {
        int blk = idx >> 5, ln = idx & 31;
        int ktp = blk % KTP, nt = blk / KTP;
        int n = nt * 8 + (ln >> 2);
        int cc = ln & 3;
        uint32_t p[4];
        #pragma unroll
        for (int h = 0; h < 2; h++) {
            int kt = 2 * ktp + h;
            float v[4];
            #pragma unroll
            for (int i = 0; i < 4; i++) {
                int k = PERM ? (8 * cc + 4 * kt + i)
                             : (kt * 16 + 2 * cc + (i & 1) + (i >> 1) * 8);
                v[i] = (n < nrows && k < kin) ? W[n * kin + k] : 0.f;
            }
            p[2 * h]     = h2nr(v[0], v[1]);
            p[2 * h + 1] = h2nr(v[2], v[3]);
        }
        *(uint4*)(dst + blk * 256 + ln * 8) = make_uint4(p[0], p[1], p[2], p[3]);
    }
}

// Ws1 [16,64] nt-paired: block kt (0..3) = 256 halves.
__device__ __forceinline__ void stage_ws1(const float* __restrict__ W, __half* dst, int t)
{
    for (int idx = t; idx < 4 * 32; idx += 128) {
        int blk = idx >> 5, ln = idx & 31;
        int gg = ln >> 2, cc = ln & 3;
        int k0 = blk * 16 + 2 * cc;
        uint32_t p[4];
        #pragma unroll
        for (int ntl = 0; ntl < 2; ntl++) {
            int n = ntl * 8 + gg;
            p[2 * ntl]     = h2nr(W[n * 64 + k0],     W[n * 64 + k0 + 1]);
            p[2 * ntl + 1] = h2nr(W[n * 64 + k0 + 8], W[n * 64 + k0 + 9]);
        }
        *(uint4*)(dst + blk * 256 + ln * 8) = make_uint4(p[0], p[1], p[2], p[3]);
    }
}

// Wc0[:, :16] n-paired: block ch = n-tiles (2ch, 2ch+1), K = SH columns 0..15
__device__ __forceinline__ void stage_wc0s(const float* __restrict__ W, __half* dst, int t)
{
    for (int idx = t; idx < 4 * 32; idx += 128) {
        int blk = idx >> 5, ln = idx & 31;
        int gg = ln >> 2, cc = ln & 3;
        uint32_t p[4];
        #pragma unroll
        for (int ntl = 0; ntl < 2; ntl++) {
            int n = (2 * blk + ntl) * 8 + gg;
            p[2 * ntl]     = h2nr(W[n * 31 + 2 * cc],     W[n * 31 + 2 * cc + 1]);
            p[2 * ntl + 1] = h2nr(W[n * 31 + 2 * cc + 8], W[n * 31 + 2 * cc + 9]);
        }
        *(uint4*)(dst + blk * 256 + ln * 8) = make_uint4(p[0], p[1], p[2], p[3]);
    }
}

// Wc0[:, 16:31] n-paired: k-slot j -> col 16+j (j=15 padded 0)
__device__ __forceinline__ void stage_wc0d(const float* __restrict__ W, __half* dst, int t)
{
    for (int idx = t; idx < 4 * 32; idx += 128) {
        int blk = idx >> 5, ln = idx & 31;
        int gg = ln >> 2, cc = ln & 3;
        uint32_t p[4];
        #pragma unroll
        for (int ntl = 0; ntl < 2; ntl++) {
            int n = (2 * blk + ntl) * 8 + gg;
            float v0 = W[n * 31 + 16 + 2 * cc];
            float v1 = W[n * 31 + 16 + 2 * cc + 1];
            float v2 = W[n * 31 + 16 + 2 * cc + 8];
            float v3 = (2 * cc + 9 < 15) ? W[n * 31 + 16 + 2 * cc + 9] : 0.f;
            p[2 * ntl]     = h2nr(v0, v1);
            p[2 * ntl + 1] = h2nr(v2, v3);
        }
        *(uint4*)(dst + blk * 256 + ln * 8) = make_uint4(p[0], p[1], p[2], p[3]);
    }
}

// Wc2 [3,64] single n-tile: block kt (0..3) = 128 halves; lane uint2 {b0,b1}.
__device__ __forceinline__ void stage_wc2(const float* __restrict__ W, __half* dst, int t)
{
    for (int idx = t; idx < 4 * 32; idx += 128) {
        int blk = idx >> 5, ln = idx & 31;
        int n = ln >> 2, cc = ln & 3;
        int k0 = blk * 16 + 2 * cc;
        float v[4] = {0.f, 0.f, 0.f, 0.f};
        if (n < 3) {
            v[0] = W[n * 64 + k0];     v[1] = W[n * 64 + k0 + 1];
            v[2] = W[n * 64 + k0 + 8]; v[3] = W[n * 64 + k0 + 9];
        }
        uint2 p; p.x = h2nr(v[0], v[1]); p.y = h2nr(v[2], v[3]);
        *(uint2*)(dst + blk * 128 + ln * 4) = p;
    }
}

// 8-wide n-subchunk over 2 m-tiles: a8[2mt][4] (8 f32 regs), zero-c first mma.
// W = base of this ntl's KTP blocks (stride 256 halves).
template<int KT>
__device__ __forceinline__ void chunkN8(const uint32_t* A, const __half* W, float* a8)
{
    #pragma unroll
    for (int ktp = 0; ktp < KT / 2; ktp++) {
        uint4 b = *(const uint4*)(W + ktp * 256);
        #pragma unroll
        for (int mt = 0; mt < 2; mt++) {
            float* d = a8 + mt * 4;
            if (ktp == 0) mma16816_zc(d, A + (mt * KT) * 4, b.x, b.y);
            else          mma16816(d, A + (mt * KT + 2 * ktp) * 4, b.x, b.y);
            mma16816(d, A + (mt * KT + 2 * ktp + 1) * 4, b.z, b.w);
        }
    }
}

// pack one ntl's 8 accumulators into its half of the fragment at k-tile ch
template<int KTO>
__device__ __forceinline__ void pack8(const float* a8, uint32_t* out, int ch, int ntl)
{
    #pragma unroll
    for (int mt = 0; mt < 2; mt++) {
        uint32_t* o = out + (mt * KTO + ch) * 4 + 2 * ntl;
        o[0] = h2relu(a8[mt * 4 + 0], a8[mt * 4 + 1]);
        o[1] = h2relu(a8[mt * 4 + 2], a8[mt * 4 + 3]);
    }
}

__global__ __launch_bounds__(128, 7)
void nnrender_occ7_kernel(const float* __restrict__ df,
                          const unsigned int* __restrict__ mask,
                          const float* __restrict__ rays_d,
                          const float* __restrict__ Ws0,   // [64,32]
                          const float* __restrict__ Ws1,   // [16,64]
                          const float* __restrict__ Wc0,   // [64,31]
                          const float* __restrict__ Wc1,   // [64,64]
                          const float* __restrict__ Wc2,   // [3,64]
                          float* __restrict__ out,         // [B,S,4]
                          int n_rays)
{
    __shared__ __align__(16) __half sW[WTOT];
    __shared__ __align__(16) float  sOut[2][128][4];
    __shared__ int sScan[2][4];

    const int t = threadIdx.x;
    const int lane = t & 31;
    const int warp = t >> 5;
    const int rowb = warp * 32;
    const int g = lane >> 2, c = lane & 3;

    stage_w<8, 2, true >(Ws0, 64, 32, sW + OW0, t);
    stage_ws1(Ws1, sW + OW1, t);
    stage_wc0s(Wc0, sW + OC0S, t);
    stage_wc0d(Wc0, sW + OC0D, t);
    stage_w<8, 4, false>(Wc1, 64, 64, sW + OC1, t);
    stage_wc2(Wc2, sW + OC2, t);
    __syncthreads();

    const __half* wL8 = sW + lane * 8;   // for 256-half blocks
    const __half* wL4 = sW + lane * 4;   // for 128-half blocks

    int it = 0;
    #pragma unroll 1
    for (int ray = blockIdx.x; ray < n_rays; ray += gridDim.x, it++) {
        const int buf = it & 1;

        // ---- early loads; compress mask to a 4-bit nibble immediately ----
        uint4 mv = __ldcs((const uint4*)(mask + (size_t)ray * S_LEN + t * 4));
        unsigned int mbits = (mv.x != 0u) | ((mv.y != 0u) << 1)
                           | ((mv.z != 0u) << 2) | ((mv.w != 0u) << 3);
        float rx = rays_d[ray * 3 + 0], ry = rays_d[ray * 3 + 1], rz = rays_d[ray * 3 + 2];

        uint32_t A1[2 * 2 * 4];
        {
            const float* dfr = df + (size_t)(ray * KV) * 32 + 8 * c;
            #pragma unroll
            for (int mt = 0; mt < 2; mt++)
                #pragma unroll
                for (int half = 0; half < 2; half++) {
                    const float* rp = dfr + (rowb + mt * 16 + g + half * 8) * 32;
                    float4 v0 = __ldcs((const float4*)(rp));
                    float4 v1 = __ldcs((const float4*)(rp + 4));
                    A1[(mt * 2 + 0) * 4 + half]     = h2nr(v0.x, v0.y);
                    A1[(mt * 2 + 0) * 4 + 2 + half] = h2nr(v0.z, v0.w);
                    A1[(mt * 2 + 1) * 4 + half]     = h2nr(v1.x, v1.y);
                    A1[(mt * 2 + 1) * 4 + 2 + half] = h2nr(v1.z, v1.w);
                }
        }

        // ---- mask scan ----
        int cnt = __popc(mbits);
        int inc = cnt;
        #pragma unroll
        for (int d = 1; d < 32; d <<= 1) {
            int n = __shfl_up_sync(0xffffffffu, inc, d);
            if (lane >= d) inc += n;
        }
        if (lane == 31) sScan[buf][warp] = inc;

        // ---- branchless SH: lane needs sh[2c], sh[2c+1], sh[2c+8], sh[2c+9] ----
        uint32_t shp01, shp89;
        {
            float x = rx, y = ry, z = rz;
            float x2 = x * x, y2 = y * y, z2 = z * z;
            float xy = x * y, yz = y * z, xz = x * z;
            float xyz = xy * z;
            float tt = 1.0f - 5.0f * z2;
            float dd = x2 - y2;
            float vA = (c == 0) ? 0.28209479177387814f :
                       (c == 1) ? 0.48860251190291987f * z :
                       (c == 2) ? 1.0925484305920792f * xy :
                                  0.94617469575755997f * z2 - 0.31539156525251999f;
            float vB = (c == 0) ? -0.48860251190291987f * y :
                       (c == 1) ? -0.48860251190291987f * x :
                       (c == 2) ? -1.0925484305920792f * yz :
                                  -1.0925484305920792f * xz;
            float vC = (c == 0) ? 0.54627421529603959f * dd :
                       (c == 1) ? 2.8906114426405538f * xyz :
                       (c == 2) ? z * (1.865881662950577f * z2 - 1.1195289977703462f) :
                                  1.445305721320277f * z * dd;
            float vD = (c == 0) ? y * (0.59004358992664352f * y2 - 1.7701307697799304f * x2) :
                       (c == 1) ? 0.45704579946446572f * y * tt :
                       (c == 2) ? 0.45704579946446572f * x * tt :
                                  x * (1.7701307697799304f * y2 - 0.59004358992664352f * x2);
            shp01 = h2nr(vA, vB);
            shp89 = h2nr(vC, vD);
        }

        // ---- L1+L2 fused: dc = (relu(DF @ Ws0^T)) @ Ws1^T ----
        float dcacc[16];
        #pragma unroll
        for (int ch = 0; ch < 4; ch++) {
            uint32_t af[8];
            #pragma unroll
            for (int ntl = 0; ntl < 2; ntl++) {
                float a8[8];
                chunkN8<2>(A1, wL8 + OW0 + (2 * ch + ntl) * 256, a8);
                pack8<1>(a8, af, 0, ntl);
            }
            uint4 b = *(const uint4*)(wL8 + OW1 + ch * 256);
            #pragma unroll
            for (int mt = 0; mt < 2; mt++) {
                if (ch == 0) {
                    mma16816_zc(dcacc + (mt * 2 + 0) * 4, af + mt * 4, b.x, b.y);
                    mma16816_zc(dcacc + (mt * 2 + 1) * 4, af + mt * 4, b.z, b.w);
                } else {
                    mma16816(dcacc + (mt * 2 + 0) * 4, af + mt * 4, b.x, b.y);
                    mma16816(dcacc + (mt * 2 + 1) * 4, af + mt * 4, b.z, b.w);
                }
            }
        }

        // sigma = relu(dc[0]) (c==0 lanes)
        if (c == 0) {
            #pragma unroll
            for (int mt = 0; mt < 2; mt++) {
                sOut[buf][rowb + mt * 16 + g][0]     = fmaxf(dcacc[(mt * 2) * 4 + 0], 0.f);
                sOut[buf][rowb + mt * 16 + g + 8][0] = fmaxf(dcacc[(mt * 2) * 4 + 2], 0.f);
            }
        }

        // ---- dc part of CIN as single-k16 A fragments ----
        uint32_t A3d[2 * 4];
        {
            const int src = (lane & ~3) | ((c + 1) & 3);
            #pragma unroll
            for (int mt = 0; mt < 2; mt++) {
                const float* d0 = dcacc + (mt * 2 + 0) * 4;   // dc cols 0..7
                const float* d1 = dcacc + (mt * 2 + 1) * 4;   // dc cols 8..15
                float n00 = __shfl_sync(0xffffffffu, d0[0], src);
                float n02 = __shfl_sync(0xffffffffu, d0[2], src);
                float n10 = __shfl_sync(0xffffffffu, d1[0], src);
                float n12 = __shfl_sync(0xffffffffu, d1[2], src);
                bool last = (c == 3);
                float s0 = last ? n10 : n00;
                float s1 = last ? n12 : n02;
                float s2 = last ? 0.f : n10;
                float s3 = last ? 0.f : n12;
                uint32_t* o = A3d + mt * 4;
                o[0] = h2nr(d0[1], s0);
                o[1] = h2nr(d0[3], s1);
                o[2] = h2nr(d1[1], s2);
                o[3] = h2nr(d1[3], s3);
            }
        }

        // ---- L3 bias-fold: C1 = relu(SH@Wc0s^T + dc@Wc0d^T) -> A4 ----
        uint32_t A4[2 * 4 * 4];
        {
            uint32_t aSH[4] = { shp01, shp01, shp89, shp89 };
            #pragma unroll
            for (int ch = 0; ch < 4; ch++) {
                uint4 bs = *(const uint4*)(wL8 + OC0S + ch * 256);
                uint4 bd = *(const uint4*)(wL8 + OC0D + ch * 256);
                #pragma unroll
                for (int ntl = 0; ntl < 2; ntl++) {
                    float bf[4];
                    mma16816_zc(bf, aSH, ntl ? bs.z : bs.x, ntl ? bs.w : bs.y);
                    float a8[8];
                    #pragma unroll
                    for (int mt = 0; mt < 2; mt++)
                        mma16816_c(a8 + mt * 4, A3d + mt * 4,
                                   ntl ? bd.z : bd.x, ntl ? bd.w : bd.y, bf[0], bf[1]);
                    pack8<4>(a8, A4, ch, ntl);
                }
            }
        }

        // ---- L4+L5 fused: col = (relu(C1 @ Wc1^T)) @ Wc2^T ----
        float acc5[8];
        #pragma unroll
        for (int ch = 0; ch < 4; ch++) {
            uint32_t af[8];
            #pragma unroll
            for (int ntl = 0; ntl < 2; ntl++) {
                float a8[8];
                chunkN8<4>(A4, wL8 + OC1 + (2 * ch + ntl) * 2 * 256, a8);
                pack8<1>(a8, af, 0, ntl);
            }
            uint2 b = *(const uint2*)(wL4 + OC2 + ch * 128);
            #pragma unroll
            for (int mt = 0; mt < 2; mt++) {
                if (ch == 0) mma16816_zc(acc5 + mt * 4, af + mt * 4, b.x, b.y);
                else         mma16816(acc5 + mt * 4, af + mt * 4, b.x, b.y);
            }
        }

        // colors -> sOut
        if (c == 0) {
            #pragma unroll
            for (int mt = 0; mt < 2; mt++) {
                int r = rowb + mt * 16 + g;
                sOut[buf][r][1]     = acc5[mt * 4 + 0];
                sOut[buf][r][2]     = acc5[mt * 4 + 1];
                sOut[buf][r + 8][1] = acc5[mt * 4 + 2];
                sOut[buf][r + 8][2] = acc5[mt * 4 + 3];
            }
        } else if (c == 1) {
            #pragma unroll
            for (int mt = 0; mt < 2; mt++) {
                int r = rowb + mt * 16 + g;
                sOut[buf][r][3]     = acc5[mt * 4 + 0];
                sOut[buf][r + 8][3] = acc5[mt * 4 + 2];
            }
        }

        __syncthreads();

        // ---- scatter: thread owns output slots 4t..4t+3 ----
        int ex = inc - cnt;
        if (warp > 0) ex += sScan[buf][0];
        if (warp > 1) ex += sScan[buf][1];
        if (warp > 2) ex += sScan[buf][2];
        float4* dst = (float4*)(out + ((size_t)ray * S_LEN + 4 * t) * 4);
        #pragma unroll
        for (int j = 0; j < 4; j++) {
            float4 o = make_float4(0.f, 0.f, 0.f, 0.f);
            if ((mbits >> j) & 1u) {
                o = *(const float4*)sOut[buf][ex];
                ex++;
            }
            __stcs(dst + j, o);
        }
    }
}

extern "C" void kernel_launch(void* const* d_in, const int* in_sizes, int n_in,
                              void* d_out, int out_size)
{
    const float*        df    = (const float*)d_in[0];
    const unsigned int* mask  = (const unsigned int*)d_in[1];
    const float*        rays  = (const float*)d_in[2];
    const float*        Ws0   = (const float*)d_in[3];
    const float*        Ws1   = (const float*)d_in[4];
    const float*        Wc0   = (const float*)d_in[5];
    const float*        Wc1   = (const float*)d_in[6];
    const float*        Wc2   = (const float*)d_in[7];
    float*              out   = (float*)d_out;

    int b_rays = in_sizes[2] / 3;
    if (b_rays <= 0) b_rays = 8192;
    int blocks = NBLK < b_rays ? NBLK : b_rays;

    nnrender_occ7_kernel<<<blocks, 128>>>(df, mask, rays,
                                          Ws0, Ws1, Wc0, Wc1, Wc2, out, b_rays);
}

// round 12
// speedup vs baseline: 1.6323x; 1.6323x over previous
#include <cuda_runtime.h>
#include <cuda_fp16.h>
#include <stdint.h>

#define S_LEN 512
#define KV    128
#define NBLK  740       // 148 SMs x 5 resident blocks (persistent)

// fused weight arena offsets (halves)
#define OW0  0        // Ws0: paired-kt, 8 blocks * 256
#define OW1  2048     // Ws1: nt-paired, 4 blocks * 256
#define OC0  3072     // Wc0: paired-kt, 8 blocks * 256
#define OC1  5120     // Wc1: paired-kt, 16 blocks * 256
#define OC2  9216     // Wc2: single-nt unpaired, 4 blocks * 128
#define WTOT 9728

__device__ __forceinline__ void mma16816(float* d, const uint32_t* a,
                                         uint32_t b0, uint32_t b1) {
    asm volatile("mma.sync.aligned.m16n8k16.row.col.f32.f16.f16.f32 "
        "{%0,%1,%2,%3},{%4,%5,%6,%7},{%8,%9},{%0,%1,%2,%3};"
        : "+f"(d[0]), "+f"(d[1]), "+f"(d[2]), "+f"(d[3])
        : "r"(a[0]), "r"(a[1]), "r"(a[2]), "r"(a[3]), "r"(b0), "r"(b1));
}
// D = A*B + 0
__device__ __forceinline__ void mma16816_zc(float* d, const uint32_t* a,
                                            uint32_t b0, uint32_t b1) {
    asm volatile("mma.sync.aligned.m16n8k16.row.col.f32.f16.f16.f32 "
        "{%0,%1,%2,%3},{%4,%5,%6,%7},{%8,%9},{%10,%11,%12,%13};"
        : "=f"(d[0]), "=f"(d[1]), "=f"(d[2]), "=f"(d[3])
        : "r"(a[0]), "r"(a[1]), "r"(a[2]), "r"(a[3]), "r"(b0), "r"(b1),
          "f"(0.f), "f"(0.f), "f"(0.f), "f"(0.f));
}
__device__ __forceinline__ uint32_t h2nr(float a, float b) {
    __half2 h = __floats2half2_rn(a, b);
    return *(uint32_t*)&h;
}
__device__ __forceinline__ uint32_t h2relu(float a, float b) {
    __half2 h = __floats2half2_rn(a, b);
    h = __hmax2(h, __half2_raw{0, 0});
    return *(uint32_t*)&h;
}

// paired-kt lane-packed repack (PERM = layer-1 K permutation)
template<int NT, int KT, bool PERM>
__device__ __forceinline__ void stage_w(const float* __restrict__ W, int nrows, int kin,
                                        __half* dst, int t)
{
    constexpr int KTP = KT / 2;
    for (int idx = t; idx < NT * KTP * 32; idx += 128) {
        int blk = idx >> 5, ln = idx & 31;
        int ktp = blk % KTP, nt = blk / KTP;
        int n = nt * 8 + (ln >> 2);
        int cc = ln & 3;
        uint32_t p[4];
        #pragma unroll
        for (int h = 0; h < 2; h++) {
            int kt = 2 * ktp + h;
            float v[4];
            #pragma unroll
            for (int i = 0; i < 4; i++) {
                int k = PERM ? (8 * cc + 4 * kt + i)
                             : (kt * 16 + 2 * cc + (i & 1) + (i >> 1) * 8);
                v[i] = (n < nrows && k < kin) ? W[n * kin + k] : 0.f;
            }
            p[2 * h]     = h2nr(v[0], v[1]);
            p[2 * h + 1] = h2nr(v[2], v[3]);
        }
        *(uint4*)(dst + blk * 256 + ln * 8) = make_uint4(p[0], p[1], p[2], p[3]);
    }
}

// Ws1 [16,64] nt-paired: block kt (0..3) = 256 halves.
__device__ __forceinline__ void stage_ws1(const float* __restrict__ W, __half* dst, int t)
{
    for (int idx = t; idx < 4 * 32; idx += 128) {
        int blk = idx >> 5, ln = idx & 31;
        int gg = ln >> 2, cc = ln & 3;
        int k0 = blk * 16 + 2 * cc;
        uint32_t p[4];
        #pragma unroll
        for (int ntl = 0; ntl < 2; ntl++) {
            int n = ntl * 8 + gg;
            p[2 * ntl]     = h2nr(W[n * 64 + k0],     W[n * 64 + k0 + 1]);
            p[2 * ntl + 1] = h2nr(W[n * 64 + k0 + 8], W[n * 64 + k0 + 9]);
        }
        *(uint4*)(dst + blk * 256 + ln * 8) = make_uint4(p[0], p[1], p[2], p[3]);
    }
}

// Wc2 [3,64] single n-tile: block kt (0..3) = 128 halves; lane uint2 {b0,b1}.
__device__ __forceinline__ void stage_wc2(const float* __restrict__ W, __half* dst, int t)
{
    for (int idx = t; idx < 4 * 32; idx += 128) {
        int blk = idx >> 5, ln = idx & 31;
        int n = ln >> 2, cc = ln & 3;
        int k0 = blk * 16 + 2 * cc;
        float v[4] = {0.f, 0.f, 0.f, 0.f};
        if (n < 3) {
            v[0] = W[n * 64 + k0];     v[1] = W[n * 64 + k0 + 1];
            v[2] = W[n * 64 + k0 + 8]; v[3] = W[n * 64 + k0 + 9];
        }
        uint2 p; p.x = h2nr(v[0], v[1]); p.y = h2nr(v[2], v[3]);
        *(uint2*)(dst + blk * 128 + ln * 4) = p;
    }
}

// one 16-wide n-chunk over 2 m-tiles (zero-c first mma)
template<int KT>
__device__ __forceinline__ void chunk2n32(const uint32_t* A, const __half* W, float* acc)
{
    #pragma unroll
    for (int ntl = 0; ntl < 2; ntl++) {
        #pragma unroll
        for (int ktp = 0; ktp < KT / 2; ktp++) {
            uint4 b = *(const uint4*)(W + (ntl * (KT / 2) + ktp) * 256);
            #pragma unroll
            for (int mt = 0; mt < 2; mt++) {
                float* d = acc + (mt * 2 + ntl) * 4;
                if (ktp == 0) mma16816_zc(d, A + (mt * KT) * 4, b.x, b.y);
                else          mma16816(d, A + (mt * KT + 2 * ktp) * 4, b.x, b.y);
                mma16816(d, A + (mt * KT + 2 * ktp + 1) * 4, b.z, b.w);
            }
        }
    }
}

// pack chunk accumulators into A fragments at k-tile ch, relu
template<int KTO>
__device__ __forceinline__ void pack_chunk32(const float* acc, uint32_t* out, int ch)
{
    #pragma unroll
    for (int mt = 0; mt < 2; mt++) {
        const float* a0 = acc + (mt * 2 + 0) * 4;
        const float* a1 = acc + (mt * 2 + 1) * 4;
        uint32_t* o = out + (mt * KTO + ch) * 4;
        o[0] = h2relu(a0[0], a0[1]);
        o[1] = h2relu(a0[2], a0[3]);
        o[2] = h2relu(a1[0], a1[1]);
        o[3] = h2relu(a1[2], a1[3]);
    }
}

__global__ __launch_bounds__(128, 5)
void nnrender_ilp5_kernel(const float* __restrict__ df,
                          const unsigned int* __restrict__ mask,
                          const float* __restrict__ rays_d,
                          const float* __restrict__ Ws0,   // [64,32]
                          const float* __restrict__ Ws1,   // [16,64]
                          const float* __restrict__ Wc0,   // [64,31]
                          const float* __restrict__ Wc1,   // [64,64]
                          const float* __restrict__ Wc2,   // [3,64]
                          float* __restrict__ out,         // [B,S,4]
                          int n_rays)
{
    __shared__ __align__(16) __half sW[WTOT];
    __shared__ __align__(16) float  sOut[2][128][4];
    __shared__ int sScan[2][4];

    const int t = threadIdx.x;
    const int lane = t & 31;
    const int warp = t >> 5;
    const int rowb = warp * 32;
    const int g = lane >> 2, c = lane & 3;

    stage_w<8, 2, true >(Ws0, 64, 32, sW + OW0, t);
    stage_ws1(Ws1, sW + OW1, t);
    stage_w<8, 2, false>(Wc0, 64, 31, sW + OC0, t);
    stage_w<8, 4, false>(Wc1, 64, 64, sW + OC1, t);
    stage_wc2(Wc2, sW + OC2, t);
    __syncthreads();

    const __half* wL8 = sW + lane * 8;   // for 256-half blocks
    const __half* wL4 = sW + lane * 4;   // for 128-half blocks

    int it = 0;
    #pragma unroll 1
    for (int ray = blockIdx.x; ray < n_rays; ray += gridDim.x, it++) {
        const int buf = it & 1;

        // ---- early loads ----
        uint4 mv = __ldcs((const uint4*)(mask + (size_t)ray * S_LEN + t * 4));
        float rx = rays_d[ray * 3 + 0], ry = rays_d[ray * 3 + 1], rz = rays_d[ray * 3 + 2];

        uint32_t A1[2 * 2 * 4];
        {
            const float* dfr = df + (size_t)(ray * KV) * 32 + 8 * c;
            #pragma unroll
            for (int mt = 0; mt < 2; mt++)
                #pragma unroll
                for (int half = 0; half < 2; half++) {
                    const float* rp = dfr + (rowb + mt * 16 + g + half * 8) * 32;
                    float4 v0 = __ldcs((const float4*)(rp));
                    float4 v1 = __ldcs((const float4*)(rp + 4));
                    A1[(mt * 2 + 0) * 4 + half]     = h2nr(v0.x, v0.y);
                    A1[(mt * 2 + 0) * 4 + 2 + half] = h2nr(v0.z, v0.w);
                    A1[(mt * 2 + 1) * 4 + half]     = h2nr(v1.x, v1.y);
                    A1[(mt * 2 + 1) * 4 + 2 + half] = h2nr(v1.z, v1.w);
                }
        }

        // ---- mask scan ----
        int cnt = (mv.x != 0u) + (mv.y != 0u) + (mv.z != 0u) + (mv.w != 0u);
        int inc = cnt;
        #pragma unroll
        for (int d = 1; d < 32; d <<= 1) {
            int n = __shfl_up_sync(0xffffffffu, inc, d);
            if (lane >= d) inc += n;
        }
        if (lane == 31) sScan[buf][warp] = inc;

        // ---- L1+L2 fused: dc = (relu(DF @ Ws0^T)) @ Ws1^T ----
        // double-buffered chunk accumulators (by ch parity) -> chunks overlap
        float dcacc[16];
        float accA[16], accB[16];
        uint32_t afA[8], afB[8];
        #pragma unroll
        for (int ch = 0; ch < 4; ch++) {
            float*    acc = (ch & 1) ? accB : accA;
            uint32_t* af  = (ch & 1) ? afB  : afA;
            chunk2n32<2>(A1, wL8 + OW0 + 2 * ch * 256, acc);
            pack_chunk32<1>(acc, af, 0);
            uint4 b = *(const uint4*)(wL8 + OW1 + ch * 256);
            #pragma unroll
            for (int mt = 0; mt < 2; mt++) {
                if (ch == 0) {
                    mma16816_zc(dcacc + (mt * 2 + 0) * 4, af + mt * 4, b.x, b.y);
                    mma16816_zc(dcacc + (mt * 2 + 1) * 4, af + mt * 4, b.z, b.w);
                } else {
                    mma16816(dcacc + (mt * 2 + 0) * 4, af + mt * 4, b.x, b.y);
                    mma16816(dcacc + (mt * 2 + 1) * 4, af + mt * 4, b.z, b.w);
                }
            }
        }

        // sigma = relu(dc[0]) (c==0 lanes)
        if (c == 0) {
            #pragma unroll
            for (int mt = 0; mt < 2; mt++) {
                sOut[buf][rowb + mt * 16 + g][0]     = fmaxf(dcacc[(mt * 2) * 4 + 0], 0.f);
                sOut[buf][rowb + mt * 16 + g + 8][0] = fmaxf(dcacc[(mt * 2) * 4 + 2], 0.f);
            }
        }

        // ---- CIN = [SH(16), dc[1:16], 0] as A fragments (KT=2) ----
        uint32_t A3[2 * 2 * 4];
        {
            // branchless SH: lane needs sh[2c], sh[2c+1], sh[2c+8], sh[2c+9]
            float x = rx, y = ry, z = rz;
            float x2 = x * x, y2 = y * y, z2 = z * z;
            float xy = x * y, yz = y * z, xz = x * z;
            float xyz = xy * z;
            float tt = 1.0f - 5.0f * z2;
            float dd = x2 - y2;
            float vA = (c == 0) ? 0.28209479177387814f :
                       (c == 1) ? 0.48860251190291987f * z :
                       (c == 2) ? 1.0925484305920792f * xy :
                                  0.94617469575755997f * z2 - 0.31539156525251999f;
            float vB = (c == 0) ? -0.48860251190291987f * y :
                       (c == 1) ? -0.48860251190291987f * x :
                       (c == 2) ? -1.0925484305920792f * yz :
                                  -1.0925484305920792f * xz;
            float vC = (c == 0) ? 0.54627421529603959f * dd :
                       (c == 1) ? 2.8906114426405538f * xyz :
                       (c == 2) ? z * (1.865881662950577f * z2 - 1.1195289977703462f) :
                                  1.445305721320277f * z * dd;
            float vD = (c == 0) ? y * (0.59004358992664352f * y2 - 1.7701307697799304f * x2) :
                       (c == 1) ? 0.45704579946446572f * y * tt :
                       (c == 2) ? 0.45704579946446572f * x * tt :
                                  x * (1.7701307697799304f * y2 - 0.59004358992664352f * x2);
            uint32_t shp01 = h2nr(vA, vB);
            uint32_t shp89 = h2nr(vC, vD);

            const int src = (lane & ~3) | ((c + 1) & 3);
            #pragma unroll
            for (int mt = 0; mt < 2; mt++) {
                const float* d0 = dcacc + (mt * 2 + 0) * 4;   // dc cols 0..7
                const float* d1 = dcacc + (mt * 2 + 1) * 4;   // dc cols 8..15
                float n00 = __shfl_sync(0xffffffffu, d0[0], src);
                float n02 = __shfl_sync(0xffffffffu, d0[2], src);
                float n10 = __shfl_sync(0xffffffffu, d1[0], src);
                float n12 = __shfl_sync(0xffffffffu, d1[2], src);
                bool last = (c == 3);
                float s0 = last ? n10 : n00;
                float s1 = last ? n12 : n02;
                float s2 = last ? 0.f : n10;
                float s3 = last ? 0.f : n12;
                uint32_t* p = A3 + (mt * 2 + 0) * 4;   // kt=0: SH (row-independent)
                p[0] = shp01; p[1] = shp01; p[2] = shp89; p[3] = shp89;
                uint32_t* o = A3 + (mt * 2 + 1) * 4;   // kt=1: dc[1:16]
                o[0] = h2nr(d0[1], s0);
                o[1] = h2nr(d0[3], s1);
                o[2] = h2nr(d1[1], s2);
                o[3] = h2nr(d1[3], s3);
            }
        }

        // ---- L3: C1 = relu(CIN @ Wc0^T) -> A4 (double-buffered chunk acc) ----
        uint32_t A4[2 * 4 * 4];
        #pragma unroll
        for (int ch = 0; ch < 4; ch++) {
            float* acc = (ch & 1) ? accB : accA;
            chunk2n32<2>(A3, wL8 + OC0 + 2 * ch * 256, acc);
            pack_chunk32<4>(acc, A4, ch);
        }

        // ---- L4+L5 fused: col = (relu(C1 @ Wc1^T)) @ Wc2^T (double-buffered) ----
        float acc5[8];
        #pragma unroll
        for (int ch = 0; ch < 4; ch++) {
            float*    acc = (ch & 1) ? accB : accA;
            uint32_t* af  = (ch & 1) ? afB  : afA;
            chunk2n32<4>(A4, wL8 + OC1 + 4 * ch * 256, acc);
            pack_chunk32<1>(acc, af, 0);
            uint2 b = *(const uint2*)(wL4 + OC2 + ch * 128);
            #pragma unroll
            for (int mt = 0; mt < 2; mt++) {
                if (ch == 0) mma16816_zc(acc5 + mt * 4, af + mt * 4, b.x, b.y);
                else         mma16816(acc5 + mt * 4, af + mt * 4, b.x, b.y);
            }
        }

        // colors -> sOut
        if (c == 0) {
            #pragma unroll
            for (int mt = 0; mt < 2; mt++) {
                int r = rowb + mt * 16 + g;
                sOut[buf][r][1]     = acc5[mt * 4 + 0];
                sOut[buf][r][2]     = acc5[mt * 4 + 1];
                sOut[buf][r + 8][1] = acc5[mt * 4 + 2];
                sOut[buf][r + 8][2] = acc5[mt * 4 + 3];
            }
        } else if (c == 1) {
            #pragma unroll
            for (int mt = 0; mt < 2; mt++) {
                int r = rowb + mt * 16 + g;
                sOut[buf][r][3]     = acc5[mt * 4 + 0];
                sOut[buf][r + 8][3] = acc5[mt * 4 + 2];
            }
        }

        __syncthreads();

        // ---- scatter: thread owns output slots 4t..4t+3 ----
        int ex = inc - cnt;
        if (warp > 0) ex += sScan[buf][0];
        if (warp > 1) ex += sScan[buf][1];
        if (warp > 2) ex += sScan[buf][2];
        float4* dst = (float4*)(out + ((size_t)ray * S_LEN + 4 * t) * 4);
        unsigned int mm[4] = {mv.x, mv.y, mv.z, mv.w};
        #pragma unroll
        for (int j = 0; j < 4; j++) {
            float4 o = make_float4(0.f, 0.f, 0.f, 0.f);
            if (mm[j] != 0u) {
                o = *(const float4*)sOut[buf][ex];
                ex++;
            }
            __stcs(dst + j, o);
        }
    }
}

extern "C" void kernel_launch(void* const* d_in, const int* in_sizes, int n_in,
                              void* d_out, int out_size)
{
    const float*        df    = (const float*)d_in[0];
    const unsigned int* mask  = (const unsigned int*)d_in[1];
    const float*        rays  = (const float*)d_in[2];
    const float*        Ws0   = (const float*)d_in[3];
    const float*        Ws1   = (const float*)d_in[4];
    const float*        Wc0   = (const float*)d_in[5];
    const float*        Wc1   = (const float*)d_in[6];
    const float*        Wc2   = (const float*)d_in[7];
    float*              out   = (float*)d_out;

    int b_rays = in_sizes[2] / 3;
    if (b_rays <= 0) b_rays = 8192;
    int blocks = NBLK < b_rays ? NBLK : b_rays;

    nnrender_ilp5_kernel<<<blocks, 128>>>(df, mask, rays,
                                          Ws0, Ws1, Wc0, Wc1, Wc2, out, b_rays);
}